// round 15
// baseline (speedup 1.0000x reference)
#include <cuda_runtime.h>
#include <cuda_bf16.h>
#include <stdint.h>
#include <math.h>

#define BN 16384
#define DN 256
#define PN 512
#define CN 20
#define NSEG 8
#define SEGL (PN / NSEG)   // 64

// ---------------------------------------------------------------------------
// Device-global scratch (no allocations allowed)
// ---------------------------------------------------------------------------
__device__ float g_s2[(size_t)BN * PN];    // s[b][k] (b-major), 32 MB
__device__ float g_U[PN * CN];
__device__ float g_A[PN];
__device__ float g_g2l[PN];
__device__ float g_hx[BN];
__device__ float g_segT2[(size_t)BN * NSEG * 24];  // [b][seg][24]: T[0..19], D at 20

__device__ __nv_bfloat16 g_Xh[(size_t)BN * DN];
__device__ __nv_bfloat16 g_Wh[PN * DN];

#define SW128(off) ((off) ^ (((off) >> 3) & 0x70))

// ---------------------------------------------------------------------------
// wrappers (base sm_103 features)
// ---------------------------------------------------------------------------
__device__ __forceinline__ void ldsm_x4(uint32_t& r0, uint32_t& r1, uint32_t& r2,
                                        uint32_t& r3, uint32_t addr) {
    asm volatile("ldmatrix.sync.aligned.m8n8.x4.shared.b16 {%0,%1,%2,%3}, [%4];"
                 : "=r"(r0), "=r"(r1), "=r"(r2), "=r"(r3) : "r"(addr));
}
__device__ __forceinline__ void mma16816(float* d, const uint32_t* a, const uint32_t* b) {
    asm volatile("mma.sync.aligned.m16n8k16.row.col.f32.bf16.bf16.f32 "
                 "{%0,%1,%2,%3}, {%4,%5,%6,%7}, {%8,%9}, {%0,%1,%2,%3};"
                 : "+f"(d[0]), "+f"(d[1]), "+f"(d[2]), "+f"(d[3])
                 : "r"(a[0]), "r"(a[1]), "r"(a[2]), "r"(a[3]), "r"(b[0]), "r"(b[1]));
}
__device__ __forceinline__ uint32_t smem_u32(const void* p) {
    uint32_t a;
    asm("{ .reg .u64 t; cvta.to.shared.u64 t, %1; cvt.u32.u64 %0, t; }" : "=r"(a) : "l"(p));
    return a;
}
__device__ __forceinline__ void cp16(uint32_t dst, const void* src) {
    asm volatile("cp.async.cg.shared.global [%0], [%1], 16;" :: "r"(dst), "l"(src));
}
#define CP_COMMIT() asm volatile("cp.async.commit_group;" ::: "memory")
#define CP_WAIT(n)  asm volatile("cp.async.wait_group %0;" :: "n"(n) : "memory")

__device__ __forceinline__ uint64_t pack2(float x) {
    uint64_t r;
    asm("mov.b64 %0, {%1, %1};" : "=l"(r) : "f"(x));
    return r;
}
__device__ __forceinline__ uint64_t fma2(uint64_t a, uint64_t b, uint64_t c) {
    uint64_t d;
    asm("fma.rn.f32x2 %0, %1, %2, %3;" : "=l"(d) : "l"(a), "l"(b), "l"(c));
    return d;
}
__device__ __forceinline__ uint64_t mul2(uint64_t a, uint64_t b) {
    uint64_t d;
    asm("mul.rn.f32x2 %0, %1, %2;" : "=l"(d) : "l"(a), "l"(b));
    return d;
}
__device__ __forceinline__ void unpack2(float& lo, float& hi, uint64_t v) {
    asm("mov.b64 {%0, %1}, %2;" : "=f"(lo), "=f"(hi) : "l"(v));
}

// ---------------------------------------------------------------------------
// Prep per-prototype
// ---------------------------------------------------------------------------
__global__ void prep_proto_kernel(const float* __restrict__ W,
                                  const float* __restrict__ BETA,
                                  const float* __restrict__ alpha,
                                  const float* __restrict__ gamma) {
    int k = blockIdx.x;
    int lane = threadIdx.x;

    float sum = 0.f;
    const float4* wr = (const float4*)(W + k * DN);
#pragma unroll
    for (int i = 0; i < 2; i++) {
        float4 v = wr[lane + i * 32];
        sum += v.x * v.x + v.y * v.y + v.z * v.z + v.w * v.w;
        int base = k * DN + (lane + i * 32) * 4;
        *(__nv_bfloat162*)(g_Wh + base) =
            __nv_bfloat162(__float2bfloat16(v.x), __float2bfloat16(v.y));
        *(__nv_bfloat162*)(g_Wh + base + 2) =
            __nv_bfloat162(__float2bfloat16(v.z), __float2bfloat16(v.w));
    }
#pragma unroll
    for (int o = 16; o; o >>= 1) sum += __shfl_xor_sync(0xffffffffu, sum, o);

    float b2 = 0.f;
    if (lane < CN) {
        float bb = BETA[k * CN + lane];
        b2 = bb * bb;
    }
    float bsum = b2;
#pragma unroll
    for (int o = 16; o; o >>= 1) bsum += __shfl_xor_sync(0xffffffffu, bsum, o);
    if (lane < CN) g_U[k * CN + lane] = b2 / bsum;

    if (lane == 0) {
        float g  = gamma[k];
        float g2 = g * g;
        float ap = 0.99f / (1.f + expf(-alpha[k]));
        g_g2l[k] = g2 * 1.4426950408889634f;
        g_A[k]   = ap * expf(-g2 * 0.5f * sum);
    }
}

// ---------------------------------------------------------------------------
// Prep per-batch
// ---------------------------------------------------------------------------
__global__ void prep_x_kernel(const float* __restrict__ X) {
    int row  = blockIdx.x * 8 + (threadIdx.x >> 5);
    int lane = threadIdx.x & 31;
    float sum = 0.f;
    const float4* xr = (const float4*)(X + (size_t)row * DN);
#pragma unroll
    for (int i = 0; i < 2; i++) {
        float4 v = xr[lane + i * 32];
        sum += v.x * v.x + v.y * v.y + v.z * v.z + v.w * v.w;
        size_t base = (size_t)row * DN + (lane + i * 32) * 4;
        *(__nv_bfloat162*)(g_Xh + base) =
            __nv_bfloat162(__float2bfloat16(v.x), __float2bfloat16(v.y));
        *(__nv_bfloat162*)(g_Xh + base + 2) =
            __nv_bfloat162(__float2bfloat16(v.z), __float2bfloat16(v.w));
    }
#pragma unroll
    for (int o = 16; o; o >>= 1) sum += __shfl_xor_sync(0xffffffffu, sum, o);
    if (lane == 0) g_hx[row] = 0.5f * sum;
}

// ---------------------------------------------------------------------------
// HMMA GEMM: D[b,p] = Xh.Wh (K=256). Block 128b x 256p, 512 threads.
// cp.async chunk fills; b-major epilogue stores. (Unchanged from R14.)
// ---------------------------------------------------------------------------
#define SM_A0 0
#define SM_A1 16384
#define SM_W0 32768
#define SM_W1 65536
#define SMEM_TOTAL 98304   // 96 KB

__global__ void __launch_bounds__(512, 1)
gemm_hmma_kernel() {
    extern __shared__ char smem[];
    const uint32_t smem_base = smem_u32(smem);
    const int t    = threadIdx.x;
    const int wid  = t >> 5;
    const int lane = t & 31;
    const int wrow = wid >> 3;
    const int wcol = wid & 7;
    const int b0   = blockIdx.x * 128;
    const int p0   = blockIdx.y * 256;

    const int abase[2] = {SM_A0, SM_A1};
    const int wbase[2] = {SM_W0, SM_W1};

    float acc[4][4][4];
#pragma unroll
    for (int mt = 0; mt < 4; mt++)
#pragma unroll
        for (int nt = 0; nt < 4; nt++)
#pragma unroll
            for (int v = 0; v < 4; v++) acc[mt][nt][v] = 0.f;

    auto load_chunk = [&](int koff, int buf) {
#pragma unroll
        for (int i = 0; i < 2; i++) {
            int idx = t + i * 512;
            int row = idx >> 3, v = idx & 7;
            cp16(smem_base + abase[buf] + SW128(row * 128 + v * 16),
                 g_Xh + (size_t)(b0 + row) * DN + koff + v * 8);
        }
#pragma unroll
        for (int i = 0; i < 4; i++) {
            int idx = t + i * 512;
            int row = idx >> 3, v = idx & 7;
            cp16(smem_base + wbase[buf] + SW128(row * 128 + v * 16),
                 g_Wh + (size_t)(p0 + row) * DN + koff + v * 8);
        }
    };

    load_chunk(0, 0);
    CP_COMMIT();

    const int lm = lane & 15;
    const int lq = lane >> 4;

    for (int c = 0; c < 4; c++) {
        int cur = c & 1;
        if (c < 3) {
            load_chunk((c + 1) * 64, cur ^ 1);
            CP_COMMIT();
            CP_WAIT(1);
        } else {
            CP_WAIT(0);
        }
        __syncthreads();

        uint32_t Ab = smem_base + abase[cur];
        uint32_t Bb = smem_base + wbase[cur];
#pragma unroll
        for (int ks = 0; ks < 4; ks++) {
            uint32_t a[4][4];
#pragma unroll
            for (int mt = 0; mt < 4; mt++)
                ldsm_x4(a[mt][0], a[mt][1], a[mt][2], a[mt][3],
                        Ab + SW128((wrow * 64 + mt * 16 + lm) * 128 + ks * 32 + lq * 16));
            uint32_t br[2][4];
#pragma unroll
            for (int bt = 0; bt < 2; bt++)
                ldsm_x4(br[bt][0], br[bt][1], br[bt][2], br[bt][3],
                        Bb + SW128((wcol * 32 + bt * 16 + lm) * 128 + ks * 32 + lq * 16));
#pragma unroll
            for (int mt = 0; mt < 4; mt++) {
#pragma unroll
                for (int bt = 0; bt < 2; bt++) {
                    uint32_t f0[2] = {br[bt][0], br[bt][2]};
                    uint32_t f1[2] = {br[bt][1], br[bt][3]};
                    mma16816(acc[mt][bt * 2 + 0], a[mt], f0);
                    mma16816(acc[mt][bt * 2 + 1], a[mt], f1);
                }
            }
        }
        __syncthreads();
    }

    // --- Epilogue: exp2 + direct b-major stores ---
    float hx0[4], hx1[4];
#pragma unroll
    for (int mt = 0; mt < 4; mt++) {
        hx0[mt] = g_hx[b0 + wrow * 64 + mt * 16 + (lane >> 2)];
        hx1[mt] = g_hx[b0 + wrow * 64 + mt * 16 + (lane >> 2) + 8];
    }
    float g2l[4][2], Ap[4][2];
#pragma unroll
    for (int nt = 0; nt < 4; nt++) {
        int p = p0 + wcol * 32 + nt * 8 + (lane & 3) * 2;
        g2l[nt][0] = g_g2l[p];
        g2l[nt][1] = g_g2l[p + 1];
        Ap[nt][0]  = g_A[p];
        Ap[nt][1]  = g_A[p + 1];
    }

#pragma unroll
    for (int mt = 0; mt < 4; mt++) {
        int brow = b0 + wrow * 64 + mt * 16 + (lane >> 2);
#pragma unroll
        for (int nt = 0; nt < 4; nt++) {
            int p = p0 + wcol * 32 + nt * 8 + (lane & 3) * 2;
            float ex[4];
#pragma unroll
            for (int v = 0; v < 4; v++) {
                float hxb = (v & 2) ? hx1[mt] : hx0[mt];
                float tt = (acc[mt][nt][v] - hxb) * g2l[nt][v & 1];
                float tr = tt + 12582912.f;
                float fn = tr - 12582912.f;
                float f  = tt - fn;
                float pl = 1.3333558146e-3f;
                pl = fmaf(pl, f, 9.6181291076e-3f);
                pl = fmaf(pl, f, 5.5504108664e-2f);
                pl = fmaf(pl, f, 2.4022650696e-1f);
                pl = fmaf(pl, f, 6.9314718056e-1f);
                pl = fmaf(pl, f, 1.0f);
                int ei = __float_as_int(tr) << 23;
                ex[v] = __int_as_float(__float_as_int(pl) + ei) * Ap[nt][v & 1];
            }
            *(float2*)(&g_s2[(size_t)brow * PN + p])       = make_float2(ex[0], ex[1]);
            *(float2*)(&g_s2[(size_t)(brow + 8) * PN + p]) = make_float2(ex[2], ex[3]);
        }
    }
}

// ---------------------------------------------------------------------------
// Scan: block = 128 threads = 64 b x 2 k-halves over one 64-k segment.
// Tiny CTAs (22 KB smem) -> ~10 CTAs / 40 warps per SM for deep cross-CTA
// overlap of coalesced tile loads with product compute.
// ---------------------------------------------------------------------------
#define SCAN_PITCH 65
#define SCAN_ROWS  64
#define SCAN_TILE  (SCAN_ROWS * SCAN_PITCH)       // floats
#define SCAN_SMEM  ((SCAN_TILE + SEGL * CN) * 4)

__global__ void __launch_bounds__(128, 8)
scan_seg_kernel() {
    extern __shared__ float sm[];
    float* tile = sm;                 // 64 x 65
    float* Us   = sm + SCAN_TILE;     // 64 x 20

    const int t     = threadIdx.x;
    const int b_loc = t & 63;
    const int h     = t >> 6;         // k-half 0/1
    const int seg   = blockIdx.y;
    const int k0    = seg * SEGL;
    const int b0    = blockIdx.x * SCAN_ROWS;

    for (int i = t; i < SEGL * CN; i += 128) Us[i] = g_U[k0 * CN + i];

    // coalesced tile load: 64 rows x 64 k; 16 float4 per row, 8 per thread
#pragma unroll
    for (int i = 0; i < 8; i++) {
        int f   = t + i * 128;
        int row = f >> 4, c = f & 15;
        float4 v = *(const float4*)(g_s2 + (size_t)(b0 + row) * PN + k0 + c * 4);
        float* d = tile + row * SCAN_PITCH + c * 4;
        d[0] = v.x; d[1] = v.y; d[2] = v.z; d[3] = v.w;
    }
    __syncthreads();

    uint64_t T2[10];
    const uint64_t ONE2 = 0x3F8000003F800000ULL;
#pragma unroll
    for (int i = 0; i < 10; i++) T2[i] = ONE2;
    float D = 1.f;

    const float* trow = tile + b_loc * SCAN_PITCH + h * 32;
    const float* urow = Us + h * 32 * CN;
#pragma unroll 4
    for (int kk = 0; kk < 32; kk++) {
        float s   = trow[kk];
        float mn1 = 1.f - s;
        uint64_t s2  = pack2(s);
        uint64_t mn2 = pack2(mn1);
        const ulonglong2* u2 = (const ulonglong2*)(urow + kk * CN);
#pragma unroll
        for (int j = 0; j < 5; j++) {
            ulonglong2 up = u2[j];
            T2[j * 2 + 0] = mul2(T2[j * 2 + 0], fma2(up.x, s2, mn2));
            T2[j * 2 + 1] = mul2(T2[j * 2 + 1], fma2(up.y, s2, mn2));
        }
        D *= mn1;
    }

    // exchange: half 1 writes partials (reuse tile), half 0 merges + stores
    __syncthreads();
    float* exch = tile;   // 64 x 22
    if (h == 1) {
        float tv[20];
#pragma unroll
        for (int i = 0; i < 10; i++) unpack2(tv[i * 2], tv[i * 2 + 1], T2[i]);
        float* e = exch + b_loc * 22;
#pragma unroll
        for (int j = 0; j < 20; j++) e[j] = tv[j];
        e[20] = D;
    }
    __syncthreads();
    if (h == 0) {
        float tv[20];
#pragma unroll
        for (int i = 0; i < 10; i++) unpack2(tv[i * 2], tv[i * 2 + 1], T2[i]);
        const float* e = exch + b_loc * 22;
        float* dst = &g_segT2[((size_t)(b0 + b_loc) * NSEG + seg) * 24];
#pragma unroll
        for (int i = 0; i < 5; i++) {
            float4 v = make_float4(tv[i * 4 + 0] * e[i * 4 + 0],
                                   tv[i * 4 + 1] * e[i * 4 + 1],
                                   tv[i * 4 + 2] * e[i * 4 + 2],
                                   tv[i * 4 + 3] * e[i * 4 + 3]);
            *(float4*)(dst + i * 4) = v;
        }
        dst[20] = D * e[20];
    }
}

// ---------------------------------------------------------------------------
// Combine: 4 lanes per b, 2 segments each (contiguous reads), shfl butterfly.
// ---------------------------------------------------------------------------
__global__ void __launch_bounds__(256) combine_kernel(float* __restrict__ out) {
    const int gt  = blockIdx.x * 256 + threadIdx.x;
    const int b   = gt >> 2;
    const int sub = gt & 3;

    float T[21];
#pragma unroll
    for (int j = 0; j < 21; j++) T[j] = 1.f;

    const float* base = &g_segT2[(size_t)b * NSEG * 24];
#pragma unroll
    for (int s = 0; s < 2; s++) {
        const float* seg = base + (sub * 2 + s) * 24;
#pragma unroll
        for (int i = 0; i < 5; i++) {
            float4 v = *(const float4*)(seg + i * 4);
            T[i * 4 + 0] *= v.x;
            T[i * 4 + 1] *= v.y;
            T[i * 4 + 2] *= v.z;
            T[i * 4 + 3] *= v.w;
        }
        T[20] *= seg[20];
    }

#pragma unroll
    for (int o = 1; o <= 2; o <<= 1) {
#pragma unroll
        for (int j = 0; j < 21; j++)
            T[j] *= __shfl_xor_sync(0xffffffffu, T[j], o);
    }

    float D = T[20];
    float Ts = 0.f;
#pragma unroll
    for (int j = 0; j < 20; j++) Ts += T[j];
    float K = Ts - 19.f * D;
    float r = 1.f / K;

#pragma unroll
    for (int j = 0; j < 5; j++)
        out[b * (CN + 1) + sub * 5 + j] = (T[sub * 5 + j] - D) * r;
    if (sub == 3) out[b * (CN + 1) + CN] = D * r;
}

// ---------------------------------------------------------------------------
extern "C" void kernel_launch(void* const* d_in, const int* in_sizes, int n_in,
                              void* d_out, int out_size) {
    const float* X     = (const float*)d_in[0];
    const float* W     = (const float*)d_in[1];
    const float* BETA  = (const float*)d_in[2];
    const float* alpha = (const float*)d_in[3];
    const float* gamma = (const float*)d_in[4];
    float* out = (float*)d_out;

    cudaFuncSetAttribute(gemm_hmma_kernel,
                         cudaFuncAttributeMaxDynamicSharedMemorySize, SMEM_TOTAL);
    cudaFuncSetAttribute(scan_seg_kernel,
                         cudaFuncAttributeMaxDynamicSharedMemorySize, SCAN_SMEM);

    prep_proto_kernel<<<PN, 32>>>(W, BETA, alpha, gamma);
    prep_x_kernel<<<BN / 8, 256>>>(X);

    dim3 ggrid(BN / 128, PN / 256);
    gemm_hmma_kernel<<<ggrid, 512, SMEM_TOTAL>>>();

    dim3 sgrid(BN / SCAN_ROWS, NSEG);
    scan_seg_kernel<<<sgrid, 128, SCAN_SMEM>>>();

    combine_kernel<<<BN * 4 / 256, 256>>>(out);
}

// round 16
// speedup vs baseline: 1.0631x; 1.0631x over previous
#include <cuda_runtime.h>
#include <cuda_bf16.h>
#include <stdint.h>
#include <math.h>

#define BN 16384
#define DN 256
#define PN 512
#define CN 20
#define NSEG 2             // scan CTA covers 256 k; 2 segments total

// ---------------------------------------------------------------------------
// Device-global scratch (no allocations allowed)
// ---------------------------------------------------------------------------
__device__ float g_s2[(size_t)BN * PN];    // s[b][k] (b-major), 32 MB
__device__ float g_U[PN * CN];
__device__ float g_A[PN];
__device__ float g_g2l[PN];
__device__ float g_hx[BN];
__device__ float g_segT2[(size_t)BN * NSEG * 24];  // [b][seg][24]: T[0..19], D at 20

__device__ __nv_bfloat16 g_Xh[(size_t)BN * DN];
__device__ __nv_bfloat16 g_Wh[PN * DN];

#define SW128(off) ((off) ^ (((off) >> 3) & 0x70))

// ---------------------------------------------------------------------------
// wrappers (base sm_103 features)
// ---------------------------------------------------------------------------
__device__ __forceinline__ void ldsm_x4(uint32_t& r0, uint32_t& r1, uint32_t& r2,
                                        uint32_t& r3, uint32_t addr) {
    asm volatile("ldmatrix.sync.aligned.m8n8.x4.shared.b16 {%0,%1,%2,%3}, [%4];"
                 : "=r"(r0), "=r"(r1), "=r"(r2), "=r"(r3) : "r"(addr));
}
__device__ __forceinline__ void mma16816(float* d, const uint32_t* a, const uint32_t* b) {
    asm volatile("mma.sync.aligned.m16n8k16.row.col.f32.bf16.bf16.f32 "
                 "{%0,%1,%2,%3}, {%4,%5,%6,%7}, {%8,%9}, {%0,%1,%2,%3};"
                 : "+f"(d[0]), "+f"(d[1]), "+f"(d[2]), "+f"(d[3])
                 : "r"(a[0]), "r"(a[1]), "r"(a[2]), "r"(a[3]), "r"(b[0]), "r"(b[1]));
}
__device__ __forceinline__ uint32_t smem_u32(const void* p) {
    uint32_t a;
    asm("{ .reg .u64 t; cvta.to.shared.u64 t, %1; cvt.u32.u64 %0, t; }" : "=r"(a) : "l"(p));
    return a;
}
__device__ __forceinline__ void cp16(uint32_t dst, const void* src) {
    asm volatile("cp.async.cg.shared.global [%0], [%1], 16;" :: "r"(dst), "l"(src));
}
#define CP_COMMIT() asm volatile("cp.async.commit_group;" ::: "memory")
#define CP_WAIT(n)  asm volatile("cp.async.wait_group %0;" :: "n"(n) : "memory")

__device__ __forceinline__ uint64_t pack2(float x) {
    uint64_t r;
    asm("mov.b64 %0, {%1, %1};" : "=l"(r) : "f"(x));
    return r;
}
__device__ __forceinline__ uint64_t fma2(uint64_t a, uint64_t b, uint64_t c) {
    uint64_t d;
    asm("fma.rn.f32x2 %0, %1, %2, %3;" : "=l"(d) : "l"(a), "l"(b), "l"(c));
    return d;
}
__device__ __forceinline__ uint64_t mul2(uint64_t a, uint64_t b) {
    uint64_t d;
    asm("mul.rn.f32x2 %0, %1, %2;" : "=l"(d) : "l"(a), "l"(b));
    return d;
}
__device__ __forceinline__ void unpack2(float& lo, float& hi, uint64_t v) {
    asm("mov.b64 {%0, %1}, %2;" : "=f"(lo), "=f"(hi) : "l"(v));
}

// ---------------------------------------------------------------------------
// Prep per-prototype
// ---------------------------------------------------------------------------
__global__ void prep_proto_kernel(const float* __restrict__ W,
                                  const float* __restrict__ BETA,
                                  const float* __restrict__ alpha,
                                  const float* __restrict__ gamma) {
    int k = blockIdx.x;
    int lane = threadIdx.x;

    float sum = 0.f;
    const float4* wr = (const float4*)(W + k * DN);
#pragma unroll
    for (int i = 0; i < 2; i++) {
        float4 v = wr[lane + i * 32];
        sum += v.x * v.x + v.y * v.y + v.z * v.z + v.w * v.w;
        int base = k * DN + (lane + i * 32) * 4;
        *(__nv_bfloat162*)(g_Wh + base) =
            __nv_bfloat162(__float2bfloat16(v.x), __float2bfloat16(v.y));
        *(__nv_bfloat162*)(g_Wh + base + 2) =
            __nv_bfloat162(__float2bfloat16(v.z), __float2bfloat16(v.w));
    }
#pragma unroll
    for (int o = 16; o; o >>= 1) sum += __shfl_xor_sync(0xffffffffu, sum, o);

    float b2 = 0.f;
    if (lane < CN) {
        float bb = BETA[k * CN + lane];
        b2 = bb * bb;
    }
    float bsum = b2;
#pragma unroll
    for (int o = 16; o; o >>= 1) bsum += __shfl_xor_sync(0xffffffffu, bsum, o);
    if (lane < CN) g_U[k * CN + lane] = b2 / bsum;

    if (lane == 0) {
        float g  = gamma[k];
        float g2 = g * g;
        float ap = 0.99f / (1.f + expf(-alpha[k]));
        g_g2l[k] = g2 * 1.4426950408889634f;
        g_A[k]   = ap * expf(-g2 * 0.5f * sum);
    }
}

// ---------------------------------------------------------------------------
// Prep per-batch
// ---------------------------------------------------------------------------
__global__ void prep_x_kernel(const float* __restrict__ X) {
    int row  = blockIdx.x * 8 + (threadIdx.x >> 5);
    int lane = threadIdx.x & 31;
    float sum = 0.f;
    const float4* xr = (const float4*)(X + (size_t)row * DN);
#pragma unroll
    for (int i = 0; i < 2; i++) {
        float4 v = xr[lane + i * 32];
        sum += v.x * v.x + v.y * v.y + v.z * v.z + v.w * v.w;
        size_t base = (size_t)row * DN + (lane + i * 32) * 4;
        *(__nv_bfloat162*)(g_Xh + base) =
            __nv_bfloat162(__float2bfloat16(v.x), __float2bfloat16(v.y));
        *(__nv_bfloat162*)(g_Xh + base + 2) =
            __nv_bfloat162(__float2bfloat16(v.z), __float2bfloat16(v.w));
    }
#pragma unroll
    for (int o = 16; o; o >>= 1) sum += __shfl_xor_sync(0xffffffffu, sum, o);
    if (lane == 0) g_hx[row] = 0.5f * sum;
}

// ---------------------------------------------------------------------------
// HMMA GEMM: D[b,p] = Xh.Wh (K=256). Block 128b x 256p, 512 threads.
// cp.async chunk fills; b-major epilogue stores. (Unchanged from R14.)
// ---------------------------------------------------------------------------
#define SM_A0 0
#define SM_A1 16384
#define SM_W0 32768
#define SM_W1 65536
#define SMEM_TOTAL 98304   // 96 KB

__global__ void __launch_bounds__(512, 1)
gemm_hmma_kernel() {
    extern __shared__ char smem[];
    const uint32_t smem_base = smem_u32(smem);
    const int t    = threadIdx.x;
    const int wid  = t >> 5;
    const int lane = t & 31;
    const int wrow = wid >> 3;
    const int wcol = wid & 7;
    const int b0   = blockIdx.x * 128;
    const int p0   = blockIdx.y * 256;

    const int abase[2] = {SM_A0, SM_A1};
    const int wbase[2] = {SM_W0, SM_W1};

    float acc[4][4][4];
#pragma unroll
    for (int mt = 0; mt < 4; mt++)
#pragma unroll
        for (int nt = 0; nt < 4; nt++)
#pragma unroll
            for (int v = 0; v < 4; v++) acc[mt][nt][v] = 0.f;

    auto load_chunk = [&](int koff, int buf) {
#pragma unroll
        for (int i = 0; i < 2; i++) {
            int idx = t + i * 512;
            int row = idx >> 3, v = idx & 7;
            cp16(smem_base + abase[buf] + SW128(row * 128 + v * 16),
                 g_Xh + (size_t)(b0 + row) * DN + koff + v * 8);
        }
#pragma unroll
        for (int i = 0; i < 4; i++) {
            int idx = t + i * 512;
            int row = idx >> 3, v = idx & 7;
            cp16(smem_base + wbase[buf] + SW128(row * 128 + v * 16),
                 g_Wh + (size_t)(p0 + row) * DN + koff + v * 8);
        }
    };

    load_chunk(0, 0);
    CP_COMMIT();

    const int lm = lane & 15;
    const int lq = lane >> 4;

    for (int c = 0; c < 4; c++) {
        int cur = c & 1;
        if (c < 3) {
            load_chunk((c + 1) * 64, cur ^ 1);
            CP_COMMIT();
            CP_WAIT(1);
        } else {
            CP_WAIT(0);
        }
        __syncthreads();

        uint32_t Ab = smem_base + abase[cur];
        uint32_t Bb = smem_base + wbase[cur];
#pragma unroll
        for (int ks = 0; ks < 4; ks++) {
            uint32_t a[4][4];
#pragma unroll
            for (int mt = 0; mt < 4; mt++)
                ldsm_x4(a[mt][0], a[mt][1], a[mt][2], a[mt][3],
                        Ab + SW128((wrow * 64 + mt * 16 + lm) * 128 + ks * 32 + lq * 16));
            uint32_t br[2][4];
#pragma unroll
            for (int bt = 0; bt < 2; bt++)
                ldsm_x4(br[bt][0], br[bt][1], br[bt][2], br[bt][3],
                        Bb + SW128((wcol * 32 + bt * 16 + lm) * 128 + ks * 32 + lq * 16));
#pragma unroll
            for (int mt = 0; mt < 4; mt++) {
#pragma unroll
                for (int bt = 0; bt < 2; bt++) {
                    uint32_t f0[2] = {br[bt][0], br[bt][2]};
                    uint32_t f1[2] = {br[bt][1], br[bt][3]};
                    mma16816(acc[mt][bt * 2 + 0], a[mt], f0);
                    mma16816(acc[mt][bt * 2 + 1], a[mt], f1);
                }
            }
        }
        __syncthreads();
    }

    // --- Epilogue: exp2 + direct b-major stores ---
    float hx0[4], hx1[4];
#pragma unroll
    for (int mt = 0; mt < 4; mt++) {
        hx0[mt] = g_hx[b0 + wrow * 64 + mt * 16 + (lane >> 2)];
        hx1[mt] = g_hx[b0 + wrow * 64 + mt * 16 + (lane >> 2) + 8];
    }
    float g2l[4][2], Ap[4][2];
#pragma unroll
    for (int nt = 0; nt < 4; nt++) {
        int p = p0 + wcol * 32 + nt * 8 + (lane & 3) * 2;
        g2l[nt][0] = g_g2l[p];
        g2l[nt][1] = g_g2l[p + 1];
        Ap[nt][0]  = g_A[p];
        Ap[nt][1]  = g_A[p + 1];
    }

#pragma unroll
    for (int mt = 0; mt < 4; mt++) {
        int brow = b0 + wrow * 64 + mt * 16 + (lane >> 2);
#pragma unroll
        for (int nt = 0; nt < 4; nt++) {
            int p = p0 + wcol * 32 + nt * 8 + (lane & 3) * 2;
            float ex[4];
#pragma unroll
            for (int v = 0; v < 4; v++) {
                float hxb = (v & 2) ? hx1[mt] : hx0[mt];
                float tt = (acc[mt][nt][v] - hxb) * g2l[nt][v & 1];
                float tr = tt + 12582912.f;
                float fn = tr - 12582912.f;
                float f  = tt - fn;
                float pl = 1.3333558146e-3f;
                pl = fmaf(pl, f, 9.6181291076e-3f);
                pl = fmaf(pl, f, 5.5504108664e-2f);
                pl = fmaf(pl, f, 2.4022650696e-1f);
                pl = fmaf(pl, f, 6.9314718056e-1f);
                pl = fmaf(pl, f, 1.0f);
                int ei = __float_as_int(tr) << 23;
                ex[v] = __int_as_float(__float_as_int(pl) + ei) * Ap[nt][v & 1];
            }
            *(float2*)(&g_s2[(size_t)brow * PN + p])       = make_float2(ex[0], ex[1]);
            *(float2*)(&g_s2[(size_t)(brow + 8) * PN + p]) = make_float2(ex[2], ex[3]);
        }
    }
}

// ---------------------------------------------------------------------------
// Scan: CTA = 64 b x 256 k (4 tiles of 64 k), 128 threads = 64 b x 2 halves.
// Register-prefetched pipeline: tile sg+1 LDGs issue before the product of
// tile sg, so DRAM latency hides under ~800 cycles of product math.
// Product state accumulates across all 4 tiles; single exchange at the end.
// ---------------------------------------------------------------------------
#define SCAN_PITCH 65
#define SCAN_ROWS  64
#define SCAN_KTOT  256                           // k per CTA
#define SCAN_TILE  (SCAN_ROWS * SCAN_PITCH)      // floats
#define US_FLOATS  (SCAN_KTOT * CN)              // 5120
#define SCAN_SMEM  ((SCAN_TILE + US_FLOATS) * 4) // 37120 B

__global__ void __launch_bounds__(128, 5)
scan_seg_kernel() {
    extern __shared__ float sm[];
    float* tile = sm;                 // 64 x 65
    float* Us   = sm + SCAN_TILE;     // 256 x 20

    const int t     = threadIdx.x;
    const int b_loc = t & 63;
    const int h     = t >> 6;         // k-half within tile
    const int b0    = blockIdx.x * SCAN_ROWS;
    const int kbase = blockIdx.y * SCAN_KTOT;

    // U for all 4 tiles: 1280 float4 / 128 thr = 10 each (16B-aligned)
#pragma unroll
    for (int i = 0; i < 10; i++)
        ((float4*)Us)[t + i * 128] = ((const float4*)(g_U + kbase * CN))[t + i * 128];

    // prefetch tile 0 into registers
    float4 r[8];
#pragma unroll
    for (int i = 0; i < 8; i++) {
        int f = t + i * 128;
        int row = f >> 4, c = f & 15;
        r[i] = *(const float4*)(g_s2 + (size_t)(b0 + row) * PN + kbase + c * 4);
    }

    uint64_t T2[10];
    const uint64_t ONE2 = 0x3F8000003F800000ULL;
#pragma unroll
    for (int i = 0; i < 10; i++) T2[i] = ONE2;
    float D = 1.f;

    for (int sg = 0; sg < 4; sg++) {
        __syncthreads();   // tile free (and, at sg=0, Us ready)
#pragma unroll
        for (int i = 0; i < 8; i++) {
            int f = t + i * 128;
            int row = f >> 4, c = f & 15;
            float* d = tile + row * SCAN_PITCH + c * 4;
            d[0] = r[i].x; d[1] = r[i].y; d[2] = r[i].z; d[3] = r[i].w;
        }
        if (sg < 3) {
#pragma unroll
            for (int i = 0; i < 8; i++) {
                int f = t + i * 128;
                int row = f >> 4, c = f & 15;
                r[i] = *(const float4*)(g_s2 + (size_t)(b0 + row) * PN +
                                        kbase + (sg + 1) * 64 + c * 4);
            }
        }
        __syncthreads();   // tile ready

        const float* trow = tile + b_loc * SCAN_PITCH + h * 32;
        const float* urow = Us + (sg * 64 + h * 32) * CN;
#pragma unroll 4
        for (int kk = 0; kk < 32; kk++) {
            float s   = trow[kk];
            float mn1 = 1.f - s;
            uint64_t s2  = pack2(s);
            uint64_t mn2 = pack2(mn1);
            const ulonglong2* u2 = (const ulonglong2*)(urow + kk * CN);
#pragma unroll
            for (int j = 0; j < 5; j++) {
                ulonglong2 up = u2[j];
                T2[j * 2 + 0] = mul2(T2[j * 2 + 0], fma2(up.x, s2, mn2));
                T2[j * 2 + 1] = mul2(T2[j * 2 + 1], fma2(up.y, s2, mn2));
            }
            D *= mn1;
        }
    }

    // single exchange: half 1 -> smem, half 0 merges + stores
    __syncthreads();
    float* exch = tile;   // 64 x 22
    if (h == 1) {
        float tv[20];
#pragma unroll
        for (int i = 0; i < 10; i++) unpack2(tv[i * 2], tv[i * 2 + 1], T2[i]);
        float* e = exch + b_loc * 22;
#pragma unroll
        for (int j = 0; j < 20; j++) e[j] = tv[j];
        e[20] = D;
    }
    __syncthreads();
    if (h == 0) {
        float tv[20];
#pragma unroll
        for (int i = 0; i < 10; i++) unpack2(tv[i * 2], tv[i * 2 + 1], T2[i]);
        const float* e = exch + b_loc * 22;
        float* dst = &g_segT2[((size_t)(b0 + b_loc) * NSEG + blockIdx.y) * 24];
#pragma unroll
        for (int i = 0; i < 5; i++) {
            float4 v = make_float4(tv[i * 4 + 0] * e[i * 4 + 0],
                                   tv[i * 4 + 1] * e[i * 4 + 1],
                                   tv[i * 4 + 2] * e[i * 4 + 2],
                                   tv[i * 4 + 3] * e[i * 4 + 3]);
            *(float4*)(dst + i * 4) = v;
        }
        dst[20] = D * e[20];
    }
}

// ---------------------------------------------------------------------------
// Combine: 2 threads per b (one segment row each, contiguous 96B reads),
// 1-level shfl product, normalize, write.
// ---------------------------------------------------------------------------
__global__ void __launch_bounds__(256) combine_kernel(float* __restrict__ out) {
    const int gt  = blockIdx.x * 256 + threadIdx.x;
    const int b   = gt >> 1;
    const int sub = gt & 1;

    float T[21];
    const float* seg = &g_segT2[((size_t)b * NSEG + sub) * 24];
#pragma unroll
    for (int i = 0; i < 5; i++) {
        float4 v = *(const float4*)(seg + i * 4);
        T[i * 4 + 0] = v.x;
        T[i * 4 + 1] = v.y;
        T[i * 4 + 2] = v.z;
        T[i * 4 + 3] = v.w;
    }
    T[20] = seg[20];

#pragma unroll
    for (int j = 0; j < 21; j++)
        T[j] *= __shfl_xor_sync(0xffffffffu, T[j], 1);

    float D = T[20];
    float Ts = 0.f;
#pragma unroll
    for (int j = 0; j < 20; j++) Ts += T[j];
    float K = Ts - 19.f * D;
    float r = 1.f / K;

#pragma unroll
    for (int j = 0; j < 10; j++)
        out[b * (CN + 1) + sub * 10 + j] = (T[sub * 10 + j] - D) * r;
    if (sub == 1) out[b * (CN + 1) + CN] = D * r;
}

// ---------------------------------------------------------------------------
extern "C" void kernel_launch(void* const* d_in, const int* in_sizes, int n_in,
                              void* d_out, int out_size) {
    const float* X     = (const float*)d_in[0];
    const float* W     = (const float*)d_in[1];
    const float* BETA  = (const float*)d_in[2];
    const float* alpha = (const float*)d_in[3];
    const float* gamma = (const float*)d_in[4];
    float* out = (float*)d_out;

    cudaFuncSetAttribute(gemm_hmma_kernel,
                         cudaFuncAttributeMaxDynamicSharedMemorySize, SMEM_TOTAL);
    cudaFuncSetAttribute(scan_seg_kernel,
                         cudaFuncAttributeMaxDynamicSharedMemorySize, SCAN_SMEM);

    prep_proto_kernel<<<PN, 32>>>(W, BETA, alpha, gamma);
    prep_x_kernel<<<BN / 8, 256>>>(X);

    dim3 ggrid(BN / 128, PN / 256);
    gemm_hmma_kernel<<<ggrid, 512, SMEM_TOTAL>>>();

    dim3 sgrid(BN / SCAN_ROWS, NSEG);
    scan_seg_kernel<<<sgrid, 128, SCAN_SMEM>>>();

    combine_kernel<<<BN * 2 / 256, 256>>>(out);
}

// round 17
// speedup vs baseline: 1.1409x; 1.0732x over previous
#include <cuda_runtime.h>
#include <cuda_bf16.h>
#include <stdint.h>
#include <math.h>

#define BN 16384
#define DN 256
#define PN 512
#define CN 20
#define NSEG 4             // scan CTA covers 128 k

// ---------------------------------------------------------------------------
// Device-global scratch (no allocations allowed)
// ---------------------------------------------------------------------------
__device__ float g_s2[(size_t)BN * PN];    // s[b][k] (b-major), 32 MB
__device__ float g_U[PN * CN];
__device__ float g_A[PN];
__device__ float g_g2l[PN];
__device__ float g_hx[BN];
__device__ float g_segT2[(size_t)BN * NSEG * 24];  // [b][seg][24]: T[0..19], D at 20

__device__ __nv_bfloat16 g_Xh[(size_t)BN * DN];
__device__ __nv_bfloat16 g_Wh[PN * DN];

#define SW128(off) ((off) ^ (((off) >> 3) & 0x70))

// ---------------------------------------------------------------------------
// wrappers (base sm_103 features)
// ---------------------------------------------------------------------------
__device__ __forceinline__ void ldsm_x4(uint32_t& r0, uint32_t& r1, uint32_t& r2,
                                        uint32_t& r3, uint32_t addr) {
    asm volatile("ldmatrix.sync.aligned.m8n8.x4.shared.b16 {%0,%1,%2,%3}, [%4];"
                 : "=r"(r0), "=r"(r1), "=r"(r2), "=r"(r3) : "r"(addr));
}
__device__ __forceinline__ void mma16816(float* d, const uint32_t* a, const uint32_t* b) {
    asm volatile("mma.sync.aligned.m16n8k16.row.col.f32.bf16.bf16.f32 "
                 "{%0,%1,%2,%3}, {%4,%5,%6,%7}, {%8,%9}, {%0,%1,%2,%3};"
                 : "+f"(d[0]), "+f"(d[1]), "+f"(d[2]), "+f"(d[3])
                 : "r"(a[0]), "r"(a[1]), "r"(a[2]), "r"(a[3]), "r"(b[0]), "r"(b[1]));
}
__device__ __forceinline__ uint32_t smem_u32(const void* p) {
    uint32_t a;
    asm("{ .reg .u64 t; cvta.to.shared.u64 t, %1; cvt.u32.u64 %0, t; }" : "=r"(a) : "l"(p));
    return a;
}
__device__ __forceinline__ void cp16(uint32_t dst, const void* src) {
    asm volatile("cp.async.cg.shared.global [%0], [%1], 16;" :: "r"(dst), "l"(src));
}
#define CP_COMMIT() asm volatile("cp.async.commit_group;" ::: "memory")
#define CP_WAIT(n)  asm volatile("cp.async.wait_group %0;" :: "n"(n) : "memory")

__device__ __forceinline__ uint64_t pack2(float x) {
    uint64_t r;
    asm("mov.b64 %0, {%1, %1};" : "=l"(r) : "f"(x));
    return r;
}
__device__ __forceinline__ uint64_t fma2(uint64_t a, uint64_t b, uint64_t c) {
    uint64_t d;
    asm("fma.rn.f32x2 %0, %1, %2, %3;" : "=l"(d) : "l"(a), "l"(b), "l"(c));
    return d;
}
__device__ __forceinline__ uint64_t mul2(uint64_t a, uint64_t b) {
    uint64_t d;
    asm("mul.rn.f32x2 %0, %1, %2;" : "=l"(d) : "l"(a), "l"(b));
    return d;
}
__device__ __forceinline__ void unpack2(float& lo, float& hi, uint64_t v) {
    asm("mov.b64 {%0, %1}, %2;" : "=f"(lo), "=f"(hi) : "l"(v));
}

// ---------------------------------------------------------------------------
// Prep per-prototype
// ---------------------------------------------------------------------------
__global__ void prep_proto_kernel(const float* __restrict__ W,
                                  const float* __restrict__ BETA,
                                  const float* __restrict__ alpha,
                                  const float* __restrict__ gamma) {
    int k = blockIdx.x;
    int lane = threadIdx.x;

    float sum = 0.f;
    const float4* wr = (const float4*)(W + k * DN);
#pragma unroll
    for (int i = 0; i < 2; i++) {
        float4 v = wr[lane + i * 32];
        sum += v.x * v.x + v.y * v.y + v.z * v.z + v.w * v.w;
        int base = k * DN + (lane + i * 32) * 4;
        *(__nv_bfloat162*)(g_Wh + base) =
            __nv_bfloat162(__float2bfloat16(v.x), __float2bfloat16(v.y));
        *(__nv_bfloat162*)(g_Wh + base + 2) =
            __nv_bfloat162(__float2bfloat16(v.z), __float2bfloat16(v.w));
    }
#pragma unroll
    for (int o = 16; o; o >>= 1) sum += __shfl_xor_sync(0xffffffffu, sum, o);

    float b2 = 0.f;
    if (lane < CN) {
        float bb = BETA[k * CN + lane];
        b2 = bb * bb;
    }
    float bsum = b2;
#pragma unroll
    for (int o = 16; o; o >>= 1) bsum += __shfl_xor_sync(0xffffffffu, bsum, o);
    if (lane < CN) g_U[k * CN + lane] = b2 / bsum;

    if (lane == 0) {
        float g  = gamma[k];
        float g2 = g * g;
        float ap = 0.99f / (1.f + expf(-alpha[k]));
        g_g2l[k] = g2 * 1.4426950408889634f;
        g_A[k]   = ap * expf(-g2 * 0.5f * sum);
    }
}

// ---------------------------------------------------------------------------
// Prep per-batch
// ---------------------------------------------------------------------------
__global__ void prep_x_kernel(const float* __restrict__ X) {
    int row  = blockIdx.x * 8 + (threadIdx.x >> 5);
    int lane = threadIdx.x & 31;
    float sum = 0.f;
    const float4* xr = (const float4*)(X + (size_t)row * DN);
#pragma unroll
    for (int i = 0; i < 2; i++) {
        float4 v = xr[lane + i * 32];
        sum += v.x * v.x + v.y * v.y + v.z * v.z + v.w * v.w;
        size_t base = (size_t)row * DN + (lane + i * 32) * 4;
        *(__nv_bfloat162*)(g_Xh + base) =
            __nv_bfloat162(__float2bfloat16(v.x), __float2bfloat16(v.y));
        *(__nv_bfloat162*)(g_Xh + base + 2) =
            __nv_bfloat162(__float2bfloat16(v.z), __float2bfloat16(v.w));
    }
#pragma unroll
    for (int o = 16; o; o >>= 1) sum += __shfl_xor_sync(0xffffffffu, sum, o);
    if (lane == 0) g_hx[row] = 0.5f * sum;
}

// ---------------------------------------------------------------------------
// HMMA GEMM: D[b,p] = Xh.Wh (K=256). Block 128b x 128p, 256 threads,
// occupancy 2 (64 KB smem). cp.async fills; b-major epilogue stores.
// ---------------------------------------------------------------------------
#define SM_A0 0
#define SM_A1 16384
#define SM_W0 32768
#define SM_W1 49152
#define SMEM_TOTAL 65536   // 64 KB

__global__ void __launch_bounds__(256, 2)
gemm_hmma_kernel() {
    extern __shared__ char smem[];
    const uint32_t smem_base = smem_u32(smem);
    const int t    = threadIdx.x;
    const int wid  = t >> 5;
    const int lane = t & 31;
    const int wrow = wid >> 2;     // 0..1  -> 64 b rows each
    const int wcol = wid & 3;      // 0..3  -> 32 p cols each
    const int b0   = blockIdx.x * 128;
    const int p0   = blockIdx.y * 128;

    const int abase[2] = {SM_A0, SM_A1};
    const int wbase[2] = {SM_W0, SM_W1};

    float acc[4][4][4];
#pragma unroll
    for (int mt = 0; mt < 4; mt++)
#pragma unroll
        for (int nt = 0; nt < 4; nt++)
#pragma unroll
            for (int v = 0; v < 4; v++) acc[mt][nt][v] = 0.f;

    auto load_chunk = [&](int koff, int buf) {
#pragma unroll
        for (int i = 0; i < 4; i++) {
            int idx = t + i * 256;
            int row = idx >> 3, v = idx & 7;
            cp16(smem_base + abase[buf] + SW128(row * 128 + v * 16),
                 g_Xh + (size_t)(b0 + row) * DN + koff + v * 8);
        }
#pragma unroll
        for (int i = 0; i < 4; i++) {
            int idx = t + i * 256;
            int row = idx >> 3, v = idx & 7;
            cp16(smem_base + wbase[buf] + SW128(row * 128 + v * 16),
                 g_Wh + (size_t)(p0 + row) * DN + koff + v * 8);
        }
    };

    load_chunk(0, 0);
    CP_COMMIT();

    const int lm = lane & 15;
    const int lq = lane >> 4;

    for (int c = 0; c < 4; c++) {
        int cur = c & 1;
        if (c < 3) {
            load_chunk((c + 1) * 64, cur ^ 1);
            CP_COMMIT();
            CP_WAIT(1);
        } else {
            CP_WAIT(0);
        }
        __syncthreads();

        uint32_t Ab = smem_base + abase[cur];
        uint32_t Bb = smem_base + wbase[cur];
#pragma unroll
        for (int ks = 0; ks < 4; ks++) {
            uint32_t a[4][4];
#pragma unroll
            for (int mt = 0; mt < 4; mt++)
                ldsm_x4(a[mt][0], a[mt][1], a[mt][2], a[mt][3],
                        Ab + SW128((wrow * 64 + mt * 16 + lm) * 128 + ks * 32 + lq * 16));
            uint32_t br[2][4];
#pragma unroll
            for (int bt = 0; bt < 2; bt++)
                ldsm_x4(br[bt][0], br[bt][1], br[bt][2], br[bt][3],
                        Bb + SW128((wcol * 32 + bt * 16 + lm) * 128 + ks * 32 + lq * 16));
#pragma unroll
            for (int mt = 0; mt < 4; mt++) {
#pragma unroll
                for (int bt = 0; bt < 2; bt++) {
                    uint32_t f0[2] = {br[bt][0], br[bt][2]};
                    uint32_t f1[2] = {br[bt][1], br[bt][3]};
                    mma16816(acc[mt][bt * 2 + 0], a[mt], f0);
                    mma16816(acc[mt][bt * 2 + 1], a[mt], f1);
                }
            }
        }
        __syncthreads();
    }

    // --- Epilogue: exp2 + direct b-major stores ---
    float hx0[4], hx1[4];
#pragma unroll
    for (int mt = 0; mt < 4; mt++) {
        hx0[mt] = g_hx[b0 + wrow * 64 + mt * 16 + (lane >> 2)];
        hx1[mt] = g_hx[b0 + wrow * 64 + mt * 16 + (lane >> 2) + 8];
    }
    float g2l[4][2], Ap[4][2];
#pragma unroll
    for (int nt = 0; nt < 4; nt++) {
        int p = p0 + wcol * 32 + nt * 8 + (lane & 3) * 2;
        g2l[nt][0] = g_g2l[p];
        g2l[nt][1] = g_g2l[p + 1];
        Ap[nt][0]  = g_A[p];
        Ap[nt][1]  = g_A[p + 1];
    }

#pragma unroll
    for (int mt = 0; mt < 4; mt++) {
        int brow = b0 + wrow * 64 + mt * 16 + (lane >> 2);
#pragma unroll
        for (int nt = 0; nt < 4; nt++) {
            int p = p0 + wcol * 32 + nt * 8 + (lane & 3) * 2;
            float ex[4];
#pragma unroll
            for (int v = 0; v < 4; v++) {
                float hxb = (v & 2) ? hx1[mt] : hx0[mt];
                float tt = (acc[mt][nt][v] - hxb) * g2l[nt][v & 1];
                float tr = tt + 12582912.f;
                float fn = tr - 12582912.f;
                float f  = tt - fn;
                float pl = 1.3333558146e-3f;
                pl = fmaf(pl, f, 9.6181291076e-3f);
                pl = fmaf(pl, f, 5.5504108664e-2f);
                pl = fmaf(pl, f, 2.4022650696e-1f);
                pl = fmaf(pl, f, 6.9314718056e-1f);
                pl = fmaf(pl, f, 1.0f);
                int ei = __float_as_int(tr) << 23;
                ex[v] = __int_as_float(__float_as_int(pl) + ei) * Ap[nt][v & 1];
            }
            *(float2*)(&g_s2[(size_t)brow * PN + p])       = make_float2(ex[0], ex[1]);
            *(float2*)(&g_s2[(size_t)(brow + 8) * PN + p]) = make_float2(ex[2], ex[3]);
        }
    }
}

// ---------------------------------------------------------------------------
// Scan: CTA = 64 b x 128 k (2 tiles of 64 k), 128 threads = 64 b x 2 halves.
// cp.async double-buffered tiles (no register prefetch -> low regs, 5 CTAs/SM).
// Pitch 68: 16B-aligned for cp.async; 4-way LDS conflict is slack-covered.
// ---------------------------------------------------------------------------
#define SCAN_PITCH 68
#define SCAN_ROWS  64
#define SCAN_KTOT  128
#define TILE_F     (SCAN_ROWS * SCAN_PITCH)      // 4352 floats
#define US_F       (SCAN_KTOT * CN)              // 2560 floats
#define SCAN_SMEM  ((2 * TILE_F + US_F) * 4)     // 45056 B

__global__ void __launch_bounds__(128, 4)
scan_seg_kernel() {
    extern __shared__ float sm[];
    const uint32_t smem_base = smem_u32(sm);
    float* Us = sm + 2 * TILE_F;

    const int t     = threadIdx.x;
    const int b_loc = t & 63;
    const int h     = t >> 6;         // k-half within tile
    const int b0    = blockIdx.x * SCAN_ROWS;
    const int kbase = blockIdx.y * SCAN_KTOT;

    auto load_tile = [&](int sg, int buf) {
#pragma unroll
        for (int i = 0; i < 8; i++) {
            int f = t + i * 128;
            int row = f >> 4, c = f & 15;
            cp16(smem_base + (buf * TILE_F + row * SCAN_PITCH + c * 4) * 4,
                 g_s2 + (size_t)(b0 + row) * PN + kbase + sg * 64 + c * 4);
        }
    };

    // group 0: tile 0 + U; group 1: tile 1
    load_tile(0, 0);
#pragma unroll
    for (int i = 0; i < 5; i++) {
        int f = t + i * 128;
        cp16(smem_base + (2 * TILE_F + f * 4) * 4, g_U + kbase * CN + f * 4);
    }
    CP_COMMIT();
    load_tile(1, 1);
    CP_COMMIT();

    uint64_t T2[10];
    const uint64_t ONE2 = 0x3F8000003F800000ULL;
#pragma unroll
    for (int i = 0; i < 10; i++) T2[i] = ONE2;
    float D = 1.f;

#pragma unroll
    for (int sg = 0; sg < 2; sg++) {
        if (sg == 0) CP_WAIT(1);
        else         CP_WAIT(0);
        __syncthreads();

        const float* trow = sm + sg * TILE_F + b_loc * SCAN_PITCH + h * 32;
        const float* urow = Us + (sg * 64 + h * 32) * CN;
#pragma unroll 4
        for (int kk = 0; kk < 32; kk++) {
            float s   = trow[kk];
            float mn1 = 1.f - s;
            uint64_t s2  = pack2(s);
            uint64_t mn2 = pack2(mn1);
            const ulonglong2* u2 = (const ulonglong2*)(urow + kk * CN);
#pragma unroll
            for (int j = 0; j < 5; j++) {
                ulonglong2 up = u2[j];
                T2[j * 2 + 0] = mul2(T2[j * 2 + 0], fma2(up.x, s2, mn2));
                T2[j * 2 + 1] = mul2(T2[j * 2 + 1], fma2(up.y, s2, mn2));
            }
            D *= mn1;
        }
    }

    // single exchange in buf0: half 1 -> smem, half 0 merges + stores
    __syncthreads();
    float* exch = sm;   // 64 x 22
    if (h == 1) {
        float tv[20];
#pragma unroll
        for (int i = 0; i < 10; i++) unpack2(tv[i * 2], tv[i * 2 + 1], T2[i]);
        float* e = exch + b_loc * 22;
#pragma unroll
        for (int j = 0; j < 20; j++) e[j] = tv[j];
        e[20] = D;
    }
    __syncthreads();
    if (h == 0) {
        float tv[20];
#pragma unroll
        for (int i = 0; i < 10; i++) unpack2(tv[i * 2], tv[i * 2 + 1], T2[i]);
        const float* e = exch + b_loc * 22;
        float* dst = &g_segT2[((size_t)(b0 + b_loc) * NSEG + blockIdx.y) * 24];
#pragma unroll
        for (int i = 0; i < 5; i++) {
            float4 v = make_float4(tv[i * 4 + 0] * e[i * 4 + 0],
                                   tv[i * 4 + 1] * e[i * 4 + 1],
                                   tv[i * 4 + 2] * e[i * 4 + 2],
                                   tv[i * 4 + 3] * e[i * 4 + 3]);
            *(float4*)(dst + i * 4) = v;
        }
        dst[20] = D * e[20];
    }
}

// ---------------------------------------------------------------------------
// Combine: 4 lanes per b, one segment each (contiguous 96B reads),
// 2-level shfl product butterfly, normalize, write.
// ---------------------------------------------------------------------------
__global__ void __launch_bounds__(256) combine_kernel(float* __restrict__ out) {
    const int gt  = blockIdx.x * 256 + threadIdx.x;
    const int b   = gt >> 2;
    const int sub = gt & 3;

    float T[21];
    const float* seg = &g_segT2[((size_t)b * NSEG + sub) * 24];
#pragma unroll
    for (int i = 0; i < 5; i++) {
        float4 v = *(const float4*)(seg + i * 4);
        T[i * 4 + 0] = v.x;
        T[i * 4 + 1] = v.y;
        T[i * 4 + 2] = v.z;
        T[i * 4 + 3] = v.w;
    }
    T[20] = seg[20];

#pragma unroll
    for (int o = 1; o <= 2; o <<= 1) {
#pragma unroll
        for (int j = 0; j < 21; j++)
            T[j] *= __shfl_xor_sync(0xffffffffu, T[j], o);
    }

    float D = T[20];
    float Ts = 0.f;
#pragma unroll
    for (int j = 0; j < 20; j++) Ts += T[j];
    float K = Ts - 19.f * D;
    float r = 1.f / K;

#pragma unroll
    for (int j = 0; j < 5; j++)
        out[b * (CN + 1) + sub * 5 + j] = (T[sub * 5 + j] - D) * r;
    if (sub == 3) out[b * (CN + 1) + CN] = D * r;
}

// ---------------------------------------------------------------------------
extern "C" void kernel_launch(void* const* d_in, const int* in_sizes, int n_in,
                              void* d_out, int out_size) {
    const float* X     = (const float*)d_in[0];
    const float* W     = (const float*)d_in[1];
    const float* BETA  = (const float*)d_in[2];
    const float* alpha = (const float*)d_in[3];
    const float* gamma = (const float*)d_in[4];
    float* out = (float*)d_out;

    cudaFuncSetAttribute(gemm_hmma_kernel,
                         cudaFuncAttributeMaxDynamicSharedMemorySize, SMEM_TOTAL);
    cudaFuncSetAttribute(scan_seg_kernel,
                         cudaFuncAttributeMaxDynamicSharedMemorySize, SCAN_SMEM);

    prep_proto_kernel<<<PN, 32>>>(W, BETA, alpha, gamma);
    prep_x_kernel<<<BN / 8, 256>>>(X);

    dim3 ggrid(BN / 128, PN / 128);
    gemm_hmma_kernel<<<ggrid, 256, SMEM_TOTAL>>>();

    dim3 sgrid(BN / SCAN_ROWS, NSEG);
    scan_seg_kernel<<<sgrid, 128, SCAN_SMEM>>>();

    combine_kernel<<<BN * 4 / 256, 256>>>(out);
}